// round 16
// baseline (speedup 1.0000x reference)
#include <cuda_runtime.h>
#include <cuda_fp16.h>
#include <math.h>
#include <cstdint>

#define T_DIM 4096
#define C_DIM 2048
#define NF_DIM 2048
#define N3_DIM 6144

constexpr int BM = 128, BK = 64;  // BK halves -> 128B smem rows (NT)
constexpr int NST = 3;            // pipeline stages
constexpr int NTHR = 128;         // 4 warps: 2(M) x 2(N)

// Scratch (allocation-free rule: __device__ globals)
__device__ __half g_qkv[(size_t)T_DIM * N3_DIM];   // fp16 qkv (48 MB)
__device__ float g_S[(size_t)T_DIM * T_DIM];       // att logits (64 MB)
__device__ __half g_P[(size_t)T_DIM * T_DIM];      // P (fp16, *2^14)
__device__ __half g_xh[(size_t)T_DIM * C_DIM];     // x fp16
__device__ __half g_wth[(size_t)N3_DIM * C_DIM];   // W^T fp16
__device__ uint32_t g_rowmax[T_DIM];               // monotonic-uint row maxima

__device__ __forceinline__ uint32_t fmap(float f) {  // order-preserving f32->u32
  uint32_t u = __float_as_uint(f);
  return (u & 0x80000000u) ? ~u : (u | 0x80000000u);
}
__device__ __forceinline__ float funmap(uint32_t u) {
  return __uint_as_float((u & 0x80000000u) ? (u & 0x7FFFFFFFu) : ~u);
}

__device__ __forceinline__ void cpasync16(unsigned s, const void* g) {
  asm volatile("cp.async.cg.shared.global [%0], [%1], 16;\n" ::"r"(s), "l"(g));
}
__device__ __forceinline__ void cp_commit() { asm volatile("cp.async.commit_group;\n" ::); }
template <int N>
__device__ __forceinline__ void cp_wait() {
  asm volatile("cp.async.wait_group %0;\n" ::"n"(N));
}
__device__ __forceinline__ void ldsm4(uint32_t& r0, uint32_t& r1, uint32_t& r2,
                                      uint32_t& r3, unsigned addr) {
  asm volatile("ldmatrix.sync.aligned.m8n8.x4.shared.b16 {%0,%1,%2,%3}, [%4];"
               : "=r"(r0), "=r"(r1), "=r"(r2), "=r"(r3)
               : "r"(addr));
}
__device__ __forceinline__ void ldsm4t(uint32_t& r0, uint32_t& r1, uint32_t& r2,
                                       uint32_t& r3, unsigned addr) {
  asm volatile("ldmatrix.sync.aligned.m8n8.x4.trans.shared.b16 {%0,%1,%2,%3}, [%4];"
               : "=r"(r0), "=r"(r1), "=r"(r2), "=r"(r3)
               : "r"(addr));
}
__device__ __forceinline__ void mma16(float (&c)[4], const uint32_t (&a)[4],
                                      const uint32_t (&b)[2]) {
  asm volatile(
      "mma.sync.aligned.m16n8k16.row.col.f32.f16.f16.f32 "
      "{%0,%1,%2,%3}, {%4,%5,%6,%7}, {%8,%9}, {%0,%1,%2,%3};\n"
      : "+f"(c[0]), "+f"(c[1]), "+f"(c[2]), "+f"(c[3])
      : "r"(a[0]), "r"(a[1]), "r"(a[2]), "r"(a[3]), "r"(b[0]), "r"(b[1]));
}

// ---------------------------------------------------------------------------
// fp16 GEMM: D[M,N] = A[M,K] @ op(B)   (fp32 accum)
// CTA 128 x (32*NP), 128 thr (4 warps of 64 x 16*NP), 2 CTAs/SM, BK=64,
// 3-stage cp.async. A K-major. BNN=0: B[N,K] K-major (NT). BNN=1 (NP=4 only):
// B[K,N] row-major (NN, ldmatrix.trans, 64x256B swizzled tile).
// EPI: 0 -> float out * scale ; 1 -> half out + bias
// CSKIP: compact causal-triangle 1D launch + row-max side output (GEMM2)
// CK:    causal K bound + heavy-first row order (GEMM3)
// NP:    B n8-pair count per warp; BN tile = 32*NP (4 -> 128, 3 -> 96)
// ---------------------------------------------------------------------------
template <int EPI, bool CSKIP, bool CK, bool BNN, int NP>
__global__ __launch_bounds__(NTHR, 2) void gemm_h(
    const uint16_t* __restrict__ A, const uint16_t* __restrict__ B,
    void* __restrict__ Dv, const float* __restrict__ bias, float scale,
    int K, int lda, int ldb, int ldd) {
  constexpr int BN = 32 * NP;
  constexpr int ATB = BM * 128;   // 16 KB A tile
  constexpr int BTB = BN * 128;   // B tile bytes (NT: BN x 128B, NN: 64 x 2*BN B)
  constexpr int STG = ATB + BTB;
  extern __shared__ __align__(16) char smem[];
  __shared__ uint32_t smax[BM];

  int r0, c0;
  if constexpr (CSKIP) {
    // triangular decode: row y has y+1 col-blocks; t = y(y+1)/2 + c
    int t = blockIdx.x;
    int y = (int)((sqrtf(8.f * (float)t + 1.f) - 1.f) * 0.5f);
    while ((y + 1) * (y + 2) / 2 <= t) y++;
    while (y * (y + 1) / 2 > t) y--;
    r0 = y * BM;
    c0 = (t - y * (y + 1) / 2) * BN;
  } else if constexpr (CK) {
    r0 = ((int)gridDim.y - 1 - (int)blockIdx.y) * BM;  // heavy rows first
    c0 = blockIdx.x * BN;
  } else {
    r0 = blockIdx.y * BM;
    c0 = blockIdx.x * BN;
  }
  const int kend = CK ? min(K, r0 + BM) : K;
  const int nk = kend / BK;

  const int tid = threadIdx.x, lane = tid & 31, warp = tid >> 5;
  const int wm = (warp >> 1) * 64, wn = (warp & 1) * (16 * NP);
  const unsigned sbase = (unsigned)__cvta_generic_to_shared(smem);

  if constexpr (CSKIP) smax[tid] = 0u;

  auto sw_off = [](int r, int c) {  // 128B-row XOR swizzle (A, B-NT)
    return (unsigned)(r * 128 + ((c ^ (r & 7)) << 4));
  };
  auto load_stage = [&](int s, int kt) {
    unsigned b = sbase + s * STG;
#pragma unroll
    for (int i = 0; i < 8; i++) {  // A: 128 rows x 8 chunks = 1024
      int id = tid + i * NTHR, r = id >> 3, c = id & 7;
      cpasync16(b + sw_off(r, c), A + (size_t)(r0 + r) * lda + kt + c * 8);
    }
    if constexpr (BNN) {
#pragma unroll
      for (int i = 0; i < 2 * NP; i++) {  // B: 64 rows x (2*BN/16) chunks
        int id = tid + i * NTHR, r = id >> 4, c = id & 15;
        cpasync16(b + ATB + (unsigned)(r * 256 + ((c ^ (r & 7)) << 4)),
                  B + (size_t)(kt + r) * ldb + c0 + c * 8);
      }
    } else {
#pragma unroll
      for (int i = 0; i < 2 * NP; i++) {  // B: BN rows x 8 chunks
        int id = tid + i * NTHR, r = id >> 3, c = id & 7;
        cpasync16(b + ATB + sw_off(r, c), B + (size_t)(c0 + r) * ldb + kt + c * 8);
      }
    }
    cp_commit();
  };

  float acc[4][2 * NP][4];
#pragma unroll
  for (int i = 0; i < 4; i++)
#pragma unroll
    for (int j = 0; j < 2 * NP; j++)
#pragma unroll
      for (int r = 0; r < 4; r++) acc[i][j][r] = 0.f;

#pragma unroll
  for (int s = 0; s < NST - 1; s++) load_stage(s, s * BK);

  // --- per-thread ldmatrix address components ---
  const int cA = lane >> 4;
  unsigned aoff[4];
  int ax[4];
#pragma unroll
  for (int ma = 0; ma < 4; ma++) {
    int rowA = wm + ma * 16 + (lane & 15);
    aoff[ma] = (unsigned)(rowA * 128);
    ax[ma] = rowA & 7;
  }
  // B-NT components (np covers 16 B-rows each)
  const int cB = (lane >> 3) & 1;
  unsigned boff[NP];
  int bx[NP];
#pragma unroll
  for (int np = 0; np < NP; np++) {
    int rowB = wn + np * 16 + ((lane >> 4) * 8) + (lane & 7);
    boff[np] = (unsigned)(rowB * 128);
    bx[np] = rowB & 7;
  }
  // B-NN components: row = ks*16 + rnn ; chunk cb ^ (lane&7); 256B rows
  const int rnn = (lane & 7) + (((lane >> 3) & 1) << 3);
  unsigned bchunk[NP];
#pragma unroll
  for (int np = 0; np < NP; np++) {
    int cb = (wn >> 3) + np * 2 + (lane >> 4);
    bchunk[np] = (unsigned)((cb ^ (lane & 7)) << 4);
  }

  for (int k = 0; k < nk; k++) {
    cp_wait<NST - 2>();
    __syncthreads();
    if (k + NST - 1 < nk) load_stage((k + NST - 1) % NST, (k + NST - 1) * BK);
    else cp_commit();  // keep group count consistent

    const unsigned sb = sbase + (unsigned)((k % NST) * STG);
    const unsigned sA = sb, sB = sb + ATB;

#pragma unroll
    for (int ks = 0; ks < 4; ks++) {
      const int kc0 = ks * 2;
      uint32_t ah[4][4], bh[2 * NP][2];
#pragma unroll
      for (int ma = 0; ma < 4; ma++)
        ldsm4(ah[ma][0], ah[ma][1], ah[ma][2], ah[ma][3],
              sA + aoff[ma] + (unsigned)(((kc0 + cA) ^ ax[ma]) << 4));
      if constexpr (BNN) {
        const unsigned rowbyte = (unsigned)((ks * 16 + rnn) * 256);
#pragma unroll
        for (int np = 0; np < NP; np++)
          ldsm4t(bh[2 * np][0], bh[2 * np][1], bh[2 * np + 1][0], bh[2 * np + 1][1],
                 sB + rowbyte + bchunk[np]);
      } else {
#pragma unroll
        for (int np = 0; np < NP; np++)
          ldsm4(bh[2 * np][0], bh[2 * np][1], bh[2 * np + 1][0], bh[2 * np + 1][1],
                sB + boff[np] + (unsigned)(((kc0 + cB) ^ bx[np]) << 4));
      }
#pragma unroll
      for (int ma = 0; ma < 4; ma++)
#pragma unroll
        for (int na = 0; na < 2 * NP; na++) mma16(acc[ma][na], ah[ma], bh[na]);
    }
  }

  // ---- epilogue ----
  const int q = lane >> 2, t2 = lane & 3;
  if constexpr (CSKIP) __syncthreads();  // smax init visible
#pragma unroll
  for (int ma = 0; ma < 4; ma++) {
    float m0 = -3.0e38f, m1 = -3.0e38f;
#pragma unroll
    for (int na = 0; na < 2 * NP; na++) {
      const int row = r0 + wm + ma * 16 + q;
      const int col = c0 + wn + na * 8 + t2 * 2;
      float v0 = acc[ma][na][0], v1 = acc[ma][na][1];
      float v2 = acc[ma][na][2], v3 = acc[ma][na][3];
      if constexpr (EPI == 1) {
        __half* D = (__half*)Dv;
        float b0 = bias[col], b1 = bias[col + 1];
        *(__half2*)(D + (size_t)row * ldd + col) = __floats2half2_rn(v0 + b0, v1 + b1);
        *(__half2*)(D + (size_t)(row + 8) * ldd + col) = __floats2half2_rn(v2 + b0, v3 + b1);
      } else {
        float* D = (float*)Dv;
        v0 *= scale; v1 *= scale; v2 *= scale; v3 *= scale;
        *(float2*)(D + (size_t)row * ldd + col) = make_float2(v0, v1);
        *(float2*)(D + (size_t)(row + 8) * ldd + col) = make_float2(v2, v3);
        if constexpr (CSKIP) {
          m0 = fmaxf(m0, fmaxf(v0, v1));
          m1 = fmaxf(m1, fmaxf(v2, v3));
        }
      }
    }
    if constexpr (CSKIP) {
      m0 = fmaxf(m0, __shfl_xor_sync(0xffffffffu, m0, 1));
      m0 = fmaxf(m0, __shfl_xor_sync(0xffffffffu, m0, 2));
      m1 = fmaxf(m1, __shfl_xor_sync(0xffffffffu, m1, 1));
      m1 = fmaxf(m1, __shfl_xor_sync(0xffffffffu, m1, 2));
      if (t2 == 0) {
        atomicMax(&smax[wm + ma * 16 + q], fmap(m0));
        atomicMax(&smax[wm + ma * 16 + q + 8], fmap(m1));
      }
    }
  }
  if constexpr (CSKIP) {
    __syncthreads();
    atomicMax(&g_rowmax[r0 + tid], smax[tid]);
  }
}

// ---------------------------------------------------------------------------
// Prep kernels
// ---------------------------------------------------------------------------
__global__ __launch_bounds__(256) void conv_x(const float* __restrict__ in,
                                              __half* __restrict__ out, int n4) {
  int i = blockIdx.x * 256 + threadIdx.x;
  if (i < T_DIM) g_rowmax[i] = 0u;  // re-init row maxima every call
  if (i >= n4) return;
  float4 v = ((const float4*)in)[i];
  __half2* op = (__half2*)(out + (size_t)i * 4);
  op[0] = __floats2half2_rn(v.x, v.y);
  op[1] = __floats2half2_rn(v.z, v.w);
}

// W [C, N3] float -> W^T [N3, C] fp16
__global__ __launch_bounds__(256) void transpose_w(const float* __restrict__ W,
                                                   __half* __restrict__ oh) {
  __shared__ float t[32][33];
  const int bx = blockIdx.x * 32, by = blockIdx.y * 32;
  const int tx = threadIdx.x & 31, ty = threadIdx.x >> 5;
#pragma unroll
  for (int i = 0; i < 4; i++)
    t[ty + i * 8][tx] = W[(size_t)(by + ty + i * 8) * N3_DIM + bx + tx];
  __syncthreads();
#pragma unroll
  for (int i = 0; i < 4; i++) {
    float v = t[tx][ty + i * 8];
    oh[(size_t)(bx + ty + i * 8) * C_DIM + by + tx] = __float2half_rn(v);
  }
}

// ---------------------------------------------------------------------------
// Row softmax over [n_padd, row]; single S pass using precomputed row max.
// Vectorized: float4 S reads, uint2 (4xhalf) P writes. Writes bounded at the
// 128-aligned row-tile limit. Heavy rows first.
// ---------------------------------------------------------------------------
__global__ __launch_bounds__(256) void softmax_rows(const float* __restrict__ S,
                                                    __half* __restrict__ P,
                                                    const int* __restrict__ npad_p) {
  const int row = (int)gridDim.x - 1 - (int)blockIdx.x;  // longest rows first
  const int tid = threadIdx.x;
  const int npad = *npad_p;
  const float* rp = S + (size_t)row * T_DIM;
  __half* pp = P + (size_t)row * T_DIM;
  const int wend = ((row >> 7) + 1) << 7;  // GEMM3 read bound for this row
  __shared__ float red[8];
  if (row < npad) {
    for (int c = tid * 4; c < wend; c += 1024)
      *(uint2*)(pp + c) = make_uint2(0u, 0u);
    return;
  }
  const int lo = npad, hi = row;
  const float bmax = funmap(g_rowmax[row]);
  const int start = lo & ~3;

  float ev[16];
  float s = 0.f;
#pragma unroll
  for (int i = 0; i < 4; i++) {
    int c = start + (tid + i * 256) * 4;
    if (c <= hi) {
      float4 v = *(const float4*)(rp + c);
      float e0 = (c >= lo) ? __expf(v.x - bmax) * 16384.0f : 0.f;
      float e1 = (c + 1 >= lo && c + 1 <= hi) ? __expf(v.y - bmax) * 16384.0f : 0.f;
      float e2 = (c + 2 >= lo && c + 2 <= hi) ? __expf(v.z - bmax) * 16384.0f : 0.f;
      float e3 = (c + 3 >= lo && c + 3 <= hi) ? __expf(v.w - bmax) * 16384.0f : 0.f;
      ev[i * 4 + 0] = e0; ev[i * 4 + 1] = e1; ev[i * 4 + 2] = e2; ev[i * 4 + 3] = e3;
      s += (e0 + e1) + (e2 + e3);
    } else {
      ev[i * 4 + 0] = ev[i * 4 + 1] = ev[i * 4 + 2] = ev[i * 4 + 3] = 0.f;
    }
  }
#pragma unroll
  for (int o = 16; o > 0; o >>= 1) s += __shfl_xor_sync(0xffffffffu, s, o);
  if ((tid & 31) == 0) red[tid >> 5] = s;
  __syncthreads();
  float bsum = 0.f;
#pragma unroll
  for (int i = 0; i < 8; i++) bsum += red[i];
  const float inv = 16384.0f / bsum;  // final P = e/bsum * 2^14

  for (int c = tid * 4; c < start; c += 1024) *(uint2*)(pp + c) = make_uint2(0u, 0u);
#pragma unroll
  for (int i = 0; i < 4; i++) {
    int c = start + (tid + i * 256) * 4;
    if (c <= hi) {
      __half2 h0 = __floats2half2_rn(ev[i * 4 + 0] * inv, ev[i * 4 + 1] * inv);
      __half2 h1 = __floats2half2_rn(ev[i * 4 + 2] * inv, ev[i * 4 + 3] * inv);
      uint2 u;
      u.x = *(uint32_t*)&h0;
      u.y = *(uint32_t*)&h1;
      *(uint2*)(pp + c) = u;
    }
  }
  const int tail = (hi + 4) & ~3;
  for (int c = hi + 1 + tid; c < tail && c < wend; c += 256) pp[c] = __float2half(0.f);
  for (int c = tail + tid * 4; c < wend; c += 1024) *(uint2*)(pp + c) = make_uint2(0u, 0u);
}

extern "C" void kernel_launch(void* const* d_in, const int* in_sizes, int n_in,
                              void* d_out, int out_size) {
  const float* x = (const float*)d_in[0];
  const float* W = (const float*)d_in[1];
  const float* bias = (const float*)d_in[2];
  const int* n_padd = (const int*)d_in[3];
  float* y = (float*)d_out;

  __half *qkv, *P, *xh, *wth;
  float* S;
  cudaGetSymbolAddress((void**)&qkv, g_qkv);
  cudaGetSymbolAddress((void**)&S, g_S);
  cudaGetSymbolAddress((void**)&P, g_P);
  cudaGetSymbolAddress((void**)&xh, g_xh);
  cudaGetSymbolAddress((void**)&wth, g_wth);

  const float scale = 1.0f / sqrtf((float)NF_DIM);

  constexpr int SM_96 = NST * (BM * 128 + 96 * 128);    // 92160  (GEMM1, NP=3)
  constexpr int SM_128 = NST * (BM * 128 + 128 * 128);  // 98304  (GEMM2/3, NP=4)

  cudaFuncSetAttribute((const void*)gemm_h<1, false, false, false, 3>,
                       cudaFuncAttributeMaxDynamicSharedMemorySize, SM_96);
  cudaFuncSetAttribute((const void*)gemm_h<0, true, false, false, 4>,
                       cudaFuncAttributeMaxDynamicSharedMemorySize, SM_128);
  cudaFuncSetAttribute((const void*)gemm_h<0, false, true, true, 4>,
                       cudaFuncAttributeMaxDynamicSharedMemorySize, SM_128);

  // Prep: x -> fp16 (+rowmax init) ; W -> W^T fp16
  conv_x<<<(T_DIM * C_DIM / 4 + 255) / 256, 256>>>(x, xh, T_DIM * C_DIM / 4);
  transpose_w<<<dim3(N3_DIM / 32, C_DIM / 32), 256>>>(W, wth);

  // GEMM1: qkv = x @ W + b   (NT, BN=96 -> 2048 CTAs = 6.92 waves; fp16 out)
  gemm_h<1, false, false, false, 3>
      <<<dim3(N3_DIM / 96, T_DIM / BM), NTHR, SM_96>>>(
          (const uint16_t*)xh, (const uint16_t*)wth, qkv, bias, 0.f,
          C_DIM, C_DIM, C_DIM, N3_DIM);

  // GEMM2: S = (q @ k^T) * scale   (NT triangle, 528 CTAs; emits row maxima)
  gemm_h<0, true, false, false, 4><<<528, NTHR, SM_128>>>(
      (const uint16_t*)qkv, (const uint16_t*)(qkv + NF_DIM),
      S, nullptr, scale, NF_DIM, N3_DIM, N3_DIM, T_DIM);

  // Softmax -> P (fp16, *2^14, single vectorized pass using precomputed max)
  softmax_rows<<<T_DIM, 256>>>(S, P, n_padd);

  // GEMM3: y = P @ v * 2^-14   (A=P K-major; B=v NN direct from qkv)
  gemm_h<0, false, true, true, 4>
      <<<dim3(NF_DIM / 128, T_DIM / BM), NTHR, SM_128>>>(
          (const uint16_t*)P, (const uint16_t*)(qkv + 2 * NF_DIM),
          y, nullptr, 6.103515625e-05f, T_DIM, T_DIM, N3_DIM, NF_DIM);
}